// round 9
// baseline (speedup 1.0000x reference)
#include <cuda_runtime.h>
#include <cuda_bf16.h>

// Shapes (fixed by the problem)
#define B_  32
#define N_  8
#define LQ_ 256
#define LD_ 512
#define D_  768

#define D4_         (D_ / 4)            // 192 float4 per row
#define BN_STRIDE4_ (LD_ * D4_)         // float4 per (b,n) slab = 98304

// Docs kernel geometry: 8 blocks per (b,n) slab, 64 rows each, BLK = D4_
#define BLKS_PER_SLAB_ 8
#define ROWS_PER_BLK_  (LD_ / BLKS_PER_SLAB_)     // 64
#define GRID_D_        (B_ * N_ * BLKS_PER_SLAB_) // 2048
#define BLK_D_         D4_                        // 192 threads

// Prep geometry: block = (b, chunk); 8 chunks of 32 rows over Lq=256
#define NCHUNK_ 8
#define CROWS_  (LQ_ / NCHUNK_)          // 32

// Scratch (no cudaMalloc allowed)
__device__ float4 g_qpart4[NCHUNK_][B_][D4_]; // per-chunk partial column sums
__device__ float  g_sign[B_ * N_];            // +1 / -1 per (b,n)
__device__ double g_acc;
__device__ unsigned int g_ticket;

// ---------------------------------------------------------------------------
// Prep: decode is_ans (block 0), partial qsum per (b, chunk), reset acc/ticket.
// threadIdx.x == d4; float4 column loads; disjoint output slabs (no atomics,
// graph-replay safe). is_ans dtype sniffed (int32/float32/uint8) from the
// first 256 bytes, in-bounds under every candidate encoding.
// ---------------------------------------------------------------------------
__global__ void __launch_bounds__(BLK_D_) prep_kernel(
        const float4* __restrict__ q, const unsigned char* __restrict__ isa) {
    if (blockIdx.x == 0) {
        __shared__ int enc;   // 0 = int32, 1 = float32, 2 = uint8
        if (threadIdx.x == 0) {
            const unsigned int* w = (const unsigned int*)isa;
            bool all01 = true, allf = true;
            for (int i = 0; i < (B_ * N_) / 4; ++i) {   // 64 words = 256 B
                unsigned int v = w[i];
                if (v != 0u && v != 1u)           all01 = false;
                if (v != 0u && v != 0x3F800000u)  allf  = false;
            }
            enc = all01 ? 0 : (allf ? 1 : 2);
            g_acc = 0.0;
            g_ticket = 0u;
        }
        __syncthreads();
        if (threadIdx.x < B_ * N_) {
            int i = threadIdx.x;             // 0 .. 255 (only 0..191 here)
            bool ans;
            if (enc == 0)      ans = ((const int*)isa)[i]   != 0;
            else if (enc == 1) ans = ((const float*)isa)[i] != 0.0f;
            else               ans = isa[i]                 != 0;
            g_sign[i] = ans ? -1.0f : 1.0f;
            // cover indices 192..255 with the first 64 threads
            if (i < B_ * N_ - BLK_D_) {
                int j = i + BLK_D_;
                bool a2;
                if (enc == 0)      a2 = ((const int*)isa)[j]   != 0;
                else if (enc == 1) a2 = ((const float*)isa)[j] != 0.0f;
                else               a2 = isa[j]                 != 0;
                g_sign[j] = a2 ? -1.0f : 1.0f;
            }
        }
    }

    int b  = blockIdx.x >> 3;         // 0..31
    int c  = blockIdx.x & 7;          // 0..7
    int d4 = threadIdx.x;             // 0..191
    const float4* base = q + ((size_t)b * LQ_ + (size_t)c * CROWS_) * D4_ + d4;

    float4 s = make_float4(0.f, 0.f, 0.f, 0.f);
#pragma unroll 8
    for (int l = 0; l < CROWS_; ++l) {
        float4 v = __ldcs(base + (size_t)l * D4_);
        s.x += v.x; s.y += v.y; s.z += v.z; s.w += v.w;
    }
    g_qpart4[c][b][d4] = s;
}

// ---------------------------------------------------------------------------
// Docs: column-stationary streaming reduce, 8 independent LDG.128 in flight
// per thread. threadIdx.x == d4 (fixed), per-thread qsum*sign float4 in
// registers; hot loop is pure ldcs + fma + pointer add. Ticketed last block
// finalizes the scalar.
// ---------------------------------------------------------------------------
__global__ void __launch_bounds__(BLK_D_) docs_reduce_kernel(
        const float4* __restrict__ docs, float* __restrict__ out) {
    const int bn   = blockIdx.x >> 3;                 // 0..255
    const int b    = bn >> 3;
    const int d4   = threadIdx.x;                     // 0..191
    const int row0 = (blockIdx.x & 7) * ROWS_PER_BLK_;

    // Fold the 8 prep partials + sign into a register float4
    float4 qs = make_float4(0.f, 0.f, 0.f, 0.f);
#pragma unroll
    for (int c = 0; c < NCHUNK_; ++c) {
        float4 pv = g_qpart4[c][b][d4];
        qs.x += pv.x; qs.y += pv.y; qs.z += pv.z; qs.w += pv.w;
    }
    {
        float s = g_sign[bn];
        qs.x *= s; qs.y *= s; qs.z *= s; qs.w *= s;
    }

    const float4* p = docs + (size_t)bn * BN_STRIDE4_
                           + (size_t)row0 * D4_ + d4;

    float4 a0 = make_float4(0.f, 0.f, 0.f, 0.f);
    float4 a1 = make_float4(0.f, 0.f, 0.f, 0.f);
    float4 a2 = make_float4(0.f, 0.f, 0.f, 0.f);
    float4 a3 = make_float4(0.f, 0.f, 0.f, 0.f);

    for (int m = 0; m < ROWS_PER_BLK_; m += 8) {
        float4 v0 = __ldcs(p);
        float4 v1 = __ldcs(p + 1 * D4_);
        float4 v2 = __ldcs(p + 2 * D4_);
        float4 v3 = __ldcs(p + 3 * D4_);
        float4 v4 = __ldcs(p + 4 * D4_);
        float4 v5 = __ldcs(p + 5 * D4_);
        float4 v6 = __ldcs(p + 6 * D4_);
        float4 v7 = __ldcs(p + 7 * D4_);
        p += 8 * D4_;
        a0.x = fmaf(v0.x, qs.x, a0.x); a0.y = fmaf(v0.y, qs.y, a0.y);
        a0.z = fmaf(v0.z, qs.z, a0.z); a0.w = fmaf(v0.w, qs.w, a0.w);
        a1.x = fmaf(v1.x, qs.x, a1.x); a1.y = fmaf(v1.y, qs.y, a1.y);
        a1.z = fmaf(v1.z, qs.z, a1.z); a1.w = fmaf(v1.w, qs.w, a1.w);
        a2.x = fmaf(v2.x, qs.x, a2.x); a2.y = fmaf(v2.y, qs.y, a2.y);
        a2.z = fmaf(v2.z, qs.z, a2.z); a2.w = fmaf(v2.w, qs.w, a2.w);
        a3.x = fmaf(v3.x, qs.x, a3.x); a3.y = fmaf(v3.y, qs.y, a3.y);
        a3.z = fmaf(v3.z, qs.z, a3.z); a3.w = fmaf(v3.w, qs.w, a3.w);
        a0.x = fmaf(v4.x, qs.x, a0.x); a0.y = fmaf(v4.y, qs.y, a0.y);
        a0.z = fmaf(v4.z, qs.z, a0.z); a0.w = fmaf(v4.w, qs.w, a0.w);
        a1.x = fmaf(v5.x, qs.x, a1.x); a1.y = fmaf(v5.y, qs.y, a1.y);
        a1.z = fmaf(v5.z, qs.z, a1.z); a1.w = fmaf(v5.w, qs.w, a1.w);
        a2.x = fmaf(v6.x, qs.x, a2.x); a2.y = fmaf(v6.y, qs.y, a2.y);
        a2.z = fmaf(v6.z, qs.z, a2.z); a2.w = fmaf(v6.w, qs.w, a2.w);
        a3.x = fmaf(v7.x, qs.x, a3.x); a3.y = fmaf(v7.y, qs.y, a3.y);
        a3.z = fmaf(v7.z, qs.z, a3.z); a3.w = fmaf(v7.w, qs.w, a3.w);
    }
    float acc = ((a0.x + a0.y) + (a0.z + a0.w))
              + ((a1.x + a1.y) + (a1.z + a1.w))
              + ((a2.x + a2.y) + (a2.z + a2.w))
              + ((a3.x + a3.y) + (a3.z + a3.w));

    // warp reduce (6 warps per block)
#pragma unroll
    for (int o = 16; o > 0; o >>= 1)
        acc += __shfl_down_sync(0xFFFFFFFFu, acc, o);

    __shared__ float warp_sums[BLK_D_ / 32];
    int lane = threadIdx.x & 31;
    int wid  = threadIdx.x >> 5;
    if (lane == 0) warp_sums[wid] = acc;
    __syncthreads();

    __shared__ bool s_last;
    if (threadIdx.x == 0) {
        float v = warp_sums[0];
#pragma unroll
        for (int w = 1; w < BLK_D_ / 32; ++w) v += warp_sums[w];
        atomicAdd(&g_acc, (double)v);
        __threadfence();
        unsigned int t = atomicAdd(&g_ticket, 1u);
        s_last = (t == GRID_D_ - 1);
    }
    __syncthreads();

    if (s_last && threadIdx.x == 0) {
        __threadfence();
        out[0] = (float)(g_acc * (1.0 / ((double)LQ_ * (double)LD_)));
    }
}

extern "C" void kernel_launch(void* const* d_in, const int* in_sizes, int n_in,
                              void* d_out, int out_size) {
    const float*         questions = (const float*)d_in[0];
    const float*         docs      = (const float*)d_in[1];
    const unsigned char* is_ans    = (const unsigned char*)d_in[2];
    float* out = (float*)d_out;
    (void)in_sizes; (void)n_in; (void)out_size;

    prep_kernel<<<B_ * NCHUNK_, BLK_D_>>>((const float4*)questions, is_ans);
    docs_reduce_kernel<<<GRID_D_, BLK_D_>>>((const float4*)docs, out);
}

// round 10
// speedup vs baseline: 1.0618x; 1.0618x over previous
#include <cuda_runtime.h>
#include <cuda_bf16.h>

// Shapes (fixed by the problem)
#define B_  32
#define N_  8
#define LQ_ 256
#define LD_ 512
#define D_  768

#define D4_         (D_ / 4)            // 192 float4 per row
#define BN_STRIDE4_ (LD_ * D4_)         // float4 per (b,n) slab = 98304

// Fused-kernel geometry
#define PREP_BLKS_     (B_ * 8)                   // 256 prep blocks (b, chunk)
#define NCHUNK_        8
#define CROWS_         (LQ_ / NCHUNK_)            // 32 question rows per chunk
#define BLKS_PER_SLAB_ 8
#define ROWS_PER_BLK_  (LD_ / BLKS_PER_SLAB_)     // 64 doc rows per block
#define DOCS_BLKS_     (B_ * N_ * BLKS_PER_SLAB_) // 2048
#define GRID_T_        (PREP_BLKS_ + DOCS_BLKS_)  // 2304
#define BLK_T_         D4_                        // 192 threads

// Scratch (no cudaMalloc allowed). Counters are zero-initialized and
// self-cleaned by the last ticketed block -> graph-replay safe.
__device__ float4 g_qpart4[NCHUNK_][B_][D4_];
__device__ float  g_sign[B_ * N_];
__device__ double g_acc;
__device__ unsigned int g_ticket;
__device__ unsigned int g_prep_done;

// ---------------------------------------------------------------------------
// Single fused kernel.
//   Blocks [0, 256):    prep — decode is_ans (block 0 only) + partial qsum
//                       for (b, chunk). Streams 25 MB of questions.
//   Blocks [256, 2304): docs — raw column sums over a 64-row sub-slab
//                       (402 MB stream, no dependency on prep). Epilogue
//                       spins until prep counter hits 256 (long since done),
//                       folds qsum, dots, reduces, tickets. Last ticket
//                       writes the scalar and resets all counters.
// ---------------------------------------------------------------------------
__global__ void __launch_bounds__(BLK_T_) fused_kernel(
        const float4* __restrict__ q,
        const float4* __restrict__ docs,
        const unsigned char* __restrict__ isa,
        float* __restrict__ out) {

    if (blockIdx.x < PREP_BLKS_) {
        // ----------------- prep role -----------------
        if (blockIdx.x == 0) {
            // Decode is_ans; dtype sniffed (int32 / float32 / uint8) from the
            // first 256 bytes, in-bounds under every candidate encoding.
            __shared__ int enc;
            if (threadIdx.x == 0) {
                const unsigned int* w = (const unsigned int*)isa;
                bool all01 = true, allf = true;
                for (int i = 0; i < (B_ * N_) / 4; ++i) {
                    unsigned int v = w[i];
                    if (v != 0u && v != 1u)           all01 = false;
                    if (v != 0u && v != 0x3F800000u)  allf  = false;
                }
                enc = all01 ? 0 : (allf ? 1 : 2);
            }
            __syncthreads();
            for (int i = threadIdx.x; i < B_ * N_; i += BLK_T_) {
                bool ans;
                if (enc == 0)      ans = ((const int*)isa)[i]   != 0;
                else if (enc == 1) ans = ((const float*)isa)[i] != 0.0f;
                else               ans = isa[i]                 != 0;
                g_sign[i] = ans ? -1.0f : 1.0f;
            }
        }

        int b  = blockIdx.x >> 3;         // 0..31
        int c  = blockIdx.x & 7;          // 0..7
        int d4 = threadIdx.x;             // 0..191
        const float4* base = q + ((size_t)b * LQ_ + (size_t)c * CROWS_) * D4_ + d4;

        float4 s = make_float4(0.f, 0.f, 0.f, 0.f);
#pragma unroll 8
        for (int l = 0; l < CROWS_; ++l) {
            float4 v = __ldcs(base + (size_t)l * D4_);
            s.x += v.x; s.y += v.y; s.z += v.z; s.w += v.w;
        }
        g_qpart4[c][b][d4] = s;

        __syncthreads();                  // all block writes (incl. sign) done
        __threadfence();
        if (threadIdx.x == 0)
            atomicAdd(&g_prep_done, 1u);
        return;
    }

    // ----------------- docs role -----------------
    const int idx  = blockIdx.x - PREP_BLKS_;
    const int bn   = idx >> 3;                    // 0..255
    const int b    = bn >> 3;
    const int d4   = threadIdx.x;                 // 0..191
    const int row0 = (idx & 7) * ROWS_PER_BLK_;

    const float4* p = docs + (size_t)bn * BN_STRIDE4_
                           + (size_t)row0 * D4_ + d4;

    // Raw (unweighted) column sums — no dependency on prep.
    float4 a0 = make_float4(0.f, 0.f, 0.f, 0.f);
    float4 a1 = make_float4(0.f, 0.f, 0.f, 0.f);
    float4 a2 = make_float4(0.f, 0.f, 0.f, 0.f);
    float4 a3 = make_float4(0.f, 0.f, 0.f, 0.f);

    for (int m = 0; m < ROWS_PER_BLK_; m += 8) {
        float4 v0 = __ldcs(p);
        float4 v1 = __ldcs(p + 1 * D4_);
        float4 v2 = __ldcs(p + 2 * D4_);
        float4 v3 = __ldcs(p + 3 * D4_);
        float4 v4 = __ldcs(p + 4 * D4_);
        float4 v5 = __ldcs(p + 5 * D4_);
        float4 v6 = __ldcs(p + 6 * D4_);
        float4 v7 = __ldcs(p + 7 * D4_);
        p += 8 * D4_;
        a0.x += v0.x; a0.y += v0.y; a0.z += v0.z; a0.w += v0.w;
        a1.x += v1.x; a1.y += v1.y; a1.z += v1.z; a1.w += v1.w;
        a2.x += v2.x; a2.y += v2.y; a2.z += v2.z; a2.w += v2.w;
        a3.x += v3.x; a3.y += v3.y; a3.z += v3.z; a3.w += v3.w;
        a0.x += v4.x; a0.y += v4.y; a0.z += v4.z; a0.w += v4.w;
        a1.x += v5.x; a1.y += v5.y; a1.z += v5.z; a1.w += v5.w;
        a2.x += v6.x; a2.y += v6.y; a2.z += v6.z; a2.w += v6.w;
        a3.x += v7.x; a3.y += v7.y; a3.z += v7.z; a3.w += v7.w;
    }
    float4 sv;
    sv.x = (a0.x + a1.x) + (a2.x + a3.x);
    sv.y = (a0.y + a1.y) + (a2.y + a3.y);
    sv.z = (a0.z + a1.z) + (a2.z + a3.z);
    sv.w = (a0.w + a1.w) + (a2.w + a3.w);

    // Wait for prep (done ~5us into a ~64us stream; effectively free).
    if (threadIdx.x == 0) {
        while (*(volatile unsigned int*)&g_prep_done != PREP_BLKS_)
            __nanosleep(64);
    }
    __syncthreads();
    __threadfence();

    // Fold qsum partials + sign, then dot with the raw column sum.
    float4 qs = make_float4(0.f, 0.f, 0.f, 0.f);
#pragma unroll
    for (int c = 0; c < NCHUNK_; ++c) {
        float4 pv = g_qpart4[c][b][d4];
        qs.x += pv.x; qs.y += pv.y; qs.z += pv.z; qs.w += pv.w;
    }
    float acc = (sv.x * qs.x + sv.y * qs.y + sv.z * qs.z + sv.w * qs.w)
              * g_sign[bn];

    // warp reduce (6 warps per block)
#pragma unroll
    for (int o = 16; o > 0; o >>= 1)
        acc += __shfl_down_sync(0xFFFFFFFFu, acc, o);

    __shared__ float warp_sums[BLK_T_ / 32];
    int lane = threadIdx.x & 31;
    int wid  = threadIdx.x >> 5;
    if (lane == 0) warp_sums[wid] = acc;
    __syncthreads();

    __shared__ bool s_last;
    if (threadIdx.x == 0) {
        float v = warp_sums[0];
#pragma unroll
        for (int w = 1; w < BLK_T_ / 32; ++w) v += warp_sums[w];
        atomicAdd(&g_acc, (double)v);
        __threadfence();
        unsigned int t = atomicAdd(&g_ticket, 1u);
        s_last = (t == DOCS_BLKS_ - 1);
    }
    __syncthreads();

    if (s_last && threadIdx.x == 0) {
        __threadfence();
        out[0] = (float)(g_acc * (1.0 / ((double)LQ_ * (double)LD_)));
        // Self-clean for the next graph replay.
        g_acc = 0.0;
        g_ticket = 0u;
        g_prep_done = 0u;
        __threadfence();
    }
}

extern "C" void kernel_launch(void* const* d_in, const int* in_sizes, int n_in,
                              void* d_out, int out_size) {
    const float*         questions = (const float*)d_in[0];
    const float*         docs      = (const float*)d_in[1];
    const unsigned char* is_ans    = (const unsigned char*)d_in[2];
    float* out = (float*)d_out;
    (void)in_sizes; (void)n_in; (void)out_size;

    fused_kernel<<<GRID_T_, BLK_T_>>>((const float4*)questions,
                                      (const float4*)docs, is_ans, out);
}

// round 11
// speedup vs baseline: 1.0659x; 1.0039x over previous
#include <cuda_runtime.h>
#include <cuda_bf16.h>

// Shapes (fixed by the problem)
#define B_  32
#define N_  8
#define LQ_ 256
#define LD_ 512
#define D_  768

#define D4_         (D_ / 4)            // 192 float4 per row
#define BN_STRIDE4_ (LD_ * D4_)         // float4 per (b,n) slab = 98304

// Fused-kernel geometry
#define PREP_BLKS_     (B_ * 8)                   // 256 prep blocks (b, chunk)
#define NCHUNK_        8
#define CROWS_         (LQ_ / NCHUNK_)            // 32 question rows per chunk
#define BLKS_PER_SLAB_ 8
#define ROWS_PER_BLK_  (LD_ / BLKS_PER_SLAB_)     // 64 doc rows per block
#define DOCS_BLKS_     (B_ * N_ * BLKS_PER_SLAB_) // 2048
#define GRID_T_        (PREP_BLKS_ + DOCS_BLKS_)  // 2304
#define BLK_T_         D4_                        // 192 threads

// Scratch (no cudaMalloc allowed). Counters are zero-initialized and
// self-cleaned by the last ticketed block -> graph-replay safe.
__device__ float4 g_qpart4[NCHUNK_][B_][D4_];
__device__ float  g_sign[B_ * N_];
__device__ double g_acc;
__device__ unsigned int g_ticket;
__device__ unsigned int g_prep_done;

// ---------------------------------------------------------------------------
// Single fused kernel.
//   Blocks [0, 256):    prep — decode is_ans (block 0 only) + partial qsum
//                       for (b, chunk). Streams 25 MB of questions.
//   Blocks [256, 2304): docs — raw column sums over a 64-row sub-slab
//                       (402 MB stream, no dependency on prep). Epilogue
//                       spins until prep counter hits 256 (long since done),
//                       folds qsum, dots, reduces, tickets. Last ticket
//                       writes the scalar and resets all counters.
// __launch_bounds__(192, 5): cap regs at 68 so 5 blocks (5 independent slab
// streams, 30 KB outstanding) are resident per SM instead of 4.
// ---------------------------------------------------------------------------
__global__ void __launch_bounds__(BLK_T_, 5) fused_kernel(
        const float4* __restrict__ q,
        const float4* __restrict__ docs,
        const unsigned char* __restrict__ isa,
        float* __restrict__ out) {

    if (blockIdx.x < PREP_BLKS_) {
        // ----------------- prep role -----------------
        if (blockIdx.x == 0) {
            // Decode is_ans; dtype sniffed (int32 / float32 / uint8) from the
            // first 256 bytes, in-bounds under every candidate encoding.
            __shared__ int enc;
            if (threadIdx.x == 0) {
                const unsigned int* w = (const unsigned int*)isa;
                bool all01 = true, allf = true;
                for (int i = 0; i < (B_ * N_) / 4; ++i) {
                    unsigned int v = w[i];
                    if (v != 0u && v != 1u)           all01 = false;
                    if (v != 0u && v != 0x3F800000u)  allf  = false;
                }
                enc = all01 ? 0 : (allf ? 1 : 2);
            }
            __syncthreads();
            for (int i = threadIdx.x; i < B_ * N_; i += BLK_T_) {
                bool ans;
                if (enc == 0)      ans = ((const int*)isa)[i]   != 0;
                else if (enc == 1) ans = ((const float*)isa)[i] != 0.0f;
                else               ans = isa[i]                 != 0;
                g_sign[i] = ans ? -1.0f : 1.0f;
            }
        }

        int b  = blockIdx.x >> 3;         // 0..31
        int c  = blockIdx.x & 7;          // 0..7
        int d4 = threadIdx.x;             // 0..191
        const float4* base = q + ((size_t)b * LQ_ + (size_t)c * CROWS_) * D4_ + d4;

        float4 s = make_float4(0.f, 0.f, 0.f, 0.f);
#pragma unroll 8
        for (int l = 0; l < CROWS_; ++l) {
            float4 v = __ldcs(base + (size_t)l * D4_);
            s.x += v.x; s.y += v.y; s.z += v.z; s.w += v.w;
        }
        g_qpart4[c][b][d4] = s;

        __syncthreads();                  // all block writes (incl. sign) done
        __threadfence();
        if (threadIdx.x == 0)
            atomicAdd(&g_prep_done, 1u);
        return;
    }

    // ----------------- docs role -----------------
    const int idx  = blockIdx.x - PREP_BLKS_;
    const int bn   = idx >> 3;                    // 0..255
    const int b    = bn >> 3;
    const int d4   = threadIdx.x;                 // 0..191
    const int row0 = (idx & 7) * ROWS_PER_BLK_;

    const float4* p = docs + (size_t)bn * BN_STRIDE4_
                           + (size_t)row0 * D4_ + d4;

    // Raw (unweighted) column sums — no dependency on prep.
    float4 a0 = make_float4(0.f, 0.f, 0.f, 0.f);
    float4 a1 = make_float4(0.f, 0.f, 0.f, 0.f);
    float4 a2 = make_float4(0.f, 0.f, 0.f, 0.f);
    float4 a3 = make_float4(0.f, 0.f, 0.f, 0.f);

    for (int m = 0; m < ROWS_PER_BLK_; m += 8) {
        float4 v0 = __ldcs(p);
        float4 v1 = __ldcs(p + 1 * D4_);
        float4 v2 = __ldcs(p + 2 * D4_);
        float4 v3 = __ldcs(p + 3 * D4_);
        float4 v4 = __ldcs(p + 4 * D4_);
        float4 v5 = __ldcs(p + 5 * D4_);
        float4 v6 = __ldcs(p + 6 * D4_);
        float4 v7 = __ldcs(p + 7 * D4_);
        p += 8 * D4_;
        a0.x += v0.x; a0.y += v0.y; a0.z += v0.z; a0.w += v0.w;
        a1.x += v1.x; a1.y += v1.y; a1.z += v1.z; a1.w += v1.w;
        a2.x += v2.x; a2.y += v2.y; a2.z += v2.z; a2.w += v2.w;
        a3.x += v3.x; a3.y += v3.y; a3.z += v3.z; a3.w += v3.w;
        a0.x += v4.x; a0.y += v4.y; a0.z += v4.z; a0.w += v4.w;
        a1.x += v5.x; a1.y += v5.y; a1.z += v5.z; a1.w += v5.w;
        a2.x += v6.x; a2.y += v6.y; a2.z += v6.z; a2.w += v6.w;
        a3.x += v7.x; a3.y += v7.y; a3.z += v7.z; a3.w += v7.w;
    }
    float4 sv;
    sv.x = (a0.x + a1.x) + (a2.x + a3.x);
    sv.y = (a0.y + a1.y) + (a2.y + a3.y);
    sv.z = (a0.z + a1.z) + (a2.z + a3.z);
    sv.w = (a0.w + a1.w) + (a2.w + a3.w);

    // Wait for prep (done ~5us into a ~64us stream; effectively free).
    if (threadIdx.x == 0) {
        while (*(volatile unsigned int*)&g_prep_done != PREP_BLKS_)
            __nanosleep(64);
    }
    __syncthreads();
    __threadfence();

    // Fold qsum partials + sign, then dot with the raw column sum.
    float4 qs = make_float4(0.f, 0.f, 0.f, 0.f);
#pragma unroll
    for (int c = 0; c < NCHUNK_; ++c) {
        float4 pv = g_qpart4[c][b][d4];
        qs.x += pv.x; qs.y += pv.y; qs.z += pv.z; qs.w += pv.w;
    }
    float acc = (sv.x * qs.x + sv.y * qs.y + sv.z * qs.z + sv.w * qs.w)
              * g_sign[bn];

    // warp reduce (6 warps per block)
#pragma unroll
    for (int o = 16; o > 0; o >>= 1)
        acc += __shfl_down_sync(0xFFFFFFFFu, acc, o);

    __shared__ float warp_sums[BLK_T_ / 32];
    int lane = threadIdx.x & 31;
    int wid  = threadIdx.x >> 5;
    if (lane == 0) warp_sums[wid] = acc;
    __syncthreads();

    __shared__ bool s_last;
    if (threadIdx.x == 0) {
        float v = warp_sums[0];
#pragma unroll
        for (int w = 1; w < BLK_T_ / 32; ++w) v += warp_sums[w];
        atomicAdd(&g_acc, (double)v);
        __threadfence();
        unsigned int t = atomicAdd(&g_ticket, 1u);
        s_last = (t == DOCS_BLKS_ - 1);
    }
    __syncthreads();

    if (s_last && threadIdx.x == 0) {
        __threadfence();
        out[0] = (float)(g_acc * (1.0 / ((double)LQ_ * (double)LD_)));
        // Self-clean for the next graph replay.
        g_acc = 0.0;
        g_ticket = 0u;
        g_prep_done = 0u;
        __threadfence();
    }
}

extern "C" void kernel_launch(void* const* d_in, const int* in_sizes, int n_in,
                              void* d_out, int out_size) {
    const float*         questions = (const float*)d_in[0];
    const float*         docs      = (const float*)d_in[1];
    const unsigned char* is_ans    = (const unsigned char*)d_in[2];
    float* out = (float*)d_out;
    (void)in_sizes; (void)n_in; (void)out_size;

    fused_kernel<<<GRID_T_, BLK_T_>>>((const float4*)questions,
                                      (const float4*)docs, is_ans, out);
}